// round 4
// baseline (speedup 1.0000x reference)
#include <cuda_runtime.h>
#include <cuda_bf16.h>
#include <cstdint>

#define N_NODES_MAX 50000
#define E_MAX       800000
#define NF          128
#define NC          40
#define SCAN_TILE   1024
#define NB_MAX      ((N_NODES_MAX + SCAN_TILE - 1) / SCAN_TILE)   // 49

// ---------------- scratch (static device globals; no allocation) ----------------
__device__ int   g_src[E_MAX];
__device__ int   g_dst[E_MAX];
__device__ int   g_pos[E_MAX];
__device__ int   g_col[E_MAX];
__device__ int   g_deg[N_NODES_MAX];
__device__ int   g_rowptr[N_NODES_MAX + 1];
__device__ int   g_bsum[NB_MAX];
__device__ int   g_boff[NB_MAX];
__device__ float g_dinv[N_NODES_MAX];
__device__ __align__(16) float g_hs[N_NODES_MAX * NF];
__device__ __align__(16) float g_a [N_NODES_MAX * NF];
__device__ int   g_flag64;

// ---------------- CSR build ----------------
__global__ void k_zero(int n) {
    int i = blockIdx.x * blockDim.x + threadIdx.x;
    if (i < n) g_deg[i] = 0;
}

__global__ void k_detect(const unsigned int* __restrict__ ei_words) {
    unsigned v = ei_words[2 * threadIdx.x + 1];
    unsigned mask = __ballot_sync(0xffffffffu, v != 0u);
    if (threadIdx.x == 0) g_flag64 = (mask == 0u) ? 1 : 0;
}

__global__ void k_decode(const void* __restrict__ ei, int E) {
    int e = blockIdx.x * blockDim.x + threadIdx.x;
    if (e >= E) return;
    int s, d;
    if (g_flag64) {
        const long long* p = (const long long*)ei;
        s = (int)p[e]; d = (int)p[E + e];
    } else {
        const int* p = (const int*)ei;
        s = p[e]; d = p[E + e];
    }
    g_src[e] = s;
    g_dst[e] = d;
    g_pos[e] = atomicAdd(&g_deg[d], 1);
}

__global__ void k_scan1(int n) {
    __shared__ int warpsum[32];
    int b = blockIdx.x;
    int i = b * SCAN_TILE + threadIdx.x;
    int lane = threadIdx.x & 31;
    int w    = threadIdx.x >> 5;
    int v = (i < n) ? g_deg[i] : 0;

    int incl = v;
    #pragma unroll
    for (int off = 1; off < 32; off <<= 1) {
        int t = __shfl_up_sync(0xffffffffu, incl, off);
        if (lane >= off) incl += t;
    }
    if (lane == 31) warpsum[w] = incl;
    __syncthreads();
    if (w == 0) {
        int s = warpsum[lane];
        #pragma unroll
        for (int off = 1; off < 32; off <<= 1) {
            int t = __shfl_up_sync(0xffffffffu, s, off);
            if (lane >= off) s += t;
        }
        warpsum[lane] = s;
    }
    __syncthreads();
    int excl = incl - v + (w > 0 ? warpsum[w - 1] : 0);
    if (i < n) {
        g_rowptr[i] = excl;
        g_dinv[i]   = rsqrtf(1.0f + (float)v);
    }
    if (threadIdx.x == 0) g_bsum[b] = warpsum[31];
}

__global__ void k_scan2(int nb, int n) {
    __shared__ int sh[64];
    int t = threadIdx.x;
    int v = (t < nb) ? g_bsum[t] : 0;
    sh[t] = v;
    __syncthreads();
    #pragma unroll
    for (int off = 1; off < 64; off <<= 1) {
        int a = (t >= off) ? sh[t - off] : 0;
        __syncthreads();
        sh[t] += a;
        __syncthreads();
    }
    if (t < nb) g_boff[t] = sh[t] - v;
    if (t == 63) g_rowptr[n] = sh[63];
}

__global__ void k_scan3(int n) {
    int i = blockIdx.x * SCAN_TILE + threadIdx.x;
    if (i < n) g_rowptr[i] += g_boff[blockIdx.x];
}

__global__ void k_scatter(int E) {
    int e = blockIdx.x * blockDim.x + threadIdx.x;
    if (e >= E) return;
    int d = g_dst[e];
    g_col[g_rowptr[d] + g_pos[e]] = g_src[e];
}

// ---------------- HMMA GEMM: hs[row] = dinv[row] * (X[row] @ W) ----------------
// Split-bf16, fp32 accum: D = Xh Wh + Xh Wl + Xl Wh.
// CTA tile 128x128, K=128. 8 warps in 4x2; warp tile 32 rows x 64 cols.
// smem tiles: A (row-major, 256B/row) and Bt=W^T (n-major rows of k, 256B/row),
// each stored hi/lo. 16B-chunk XOR swizzle by (row&7) -> conflict-free ldmatrix.

#define SM_AH    0
#define SM_AL    (SM_AH + 32768)
#define SM_BH    (SM_AL + 32768)
#define SM_BL    (SM_BH + 32768)
#define SM_TOTAL (SM_BL + 32768)          // 131072

__device__ __forceinline__ uint32_t sm_u32(const void* p) {
    uint32_t r;
    asm("{ .reg .u64 t; cvta.to.shared.u64 t, %1; cvt.u32.u64 %0, t; }"
        : "=r"(r) : "l"(p));
    return r;
}
// element (row, k) -> byte offset within a 128x128-bf16 tile
__device__ __forceinline__ uint32_t swz(int row, int k) {
    return (uint32_t)(row * 256 + (((k >> 3) ^ (row & 7)) << 4) + (k & 7) * 2);
}

__global__ void __launch_bounds__(256, 1)
k_gemm_mma(const float* __restrict__ Xext, const float* __restrict__ W,
           int use_internal, int n) {
    extern __shared__ char sm[];
    uint32_t smb = sm_u32(sm);
    const float* X = use_internal ? (const float*)g_a : Xext;

    int t = threadIdx.x;
    int lane = t & 31;
    int w = t >> 5;
    int row0 = blockIdx.x * 128;

    // ---- stage A = X tile [128 x 128] as hi/lo bf16 (swizzled) ----
    {
        const float4* X4 = (const float4*)X;
        for (int i = t; i < 128 * 32; i += 256) {
            int r  = i >> 5;
            int c4 = i & 31;
            int gr = row0 + r;
            float4 v = (gr < n) ? X4[gr * 32 + c4]
                                : make_float4(0.f, 0.f, 0.f, 0.f);
            int k0 = c4 * 4;
            uint32_t off = swz(r, k0);
            float f[4] = {v.x, v.y, v.z, v.w};
            __nv_bfloat16 h0 = __float2bfloat16_rn(f[0]);
            __nv_bfloat16 h1 = __float2bfloat16_rn(f[1]);
            __nv_bfloat16 h2 = __float2bfloat16_rn(f[2]);
            __nv_bfloat16 h3 = __float2bfloat16_rn(f[3]);
            __nv_bfloat162 h01, h23, l01, l23;
            h01.x = h0; h01.y = h1; h23.x = h2; h23.y = h3;
            l01.x = __float2bfloat16_rn(f[0] - __bfloat162float(h0));
            l01.y = __float2bfloat16_rn(f[1] - __bfloat162float(h1));
            l23.x = __float2bfloat16_rn(f[2] - __bfloat162float(h2));
            l23.y = __float2bfloat16_rn(f[3] - __bfloat162float(h3));
            *(__nv_bfloat162*)(sm + SM_AH + off)     = h01;
            *(__nv_bfloat162*)(sm + SM_AH + off + 4) = h23;
            *(__nv_bfloat162*)(sm + SM_AL + off)     = l01;
            *(__nv_bfloat162*)(sm + SM_AL + off + 4) = l23;
        }
    }
    // ---- stage Bt = W^T [128 n-rows x 128 k] as hi/lo bf16 (swizzled) ----
    {
        for (int i = t; i < 128 * 128; i += 256) {
            int k  = i >> 7;
            int nn = i & 127;
            float v = W[i];                        // W[k][nn], coalesced
            __nv_bfloat16 h = __float2bfloat16_rn(v);
            __nv_bfloat16 l = __float2bfloat16_rn(v - __bfloat162float(h));
            uint32_t off = swz(nn, k);
            *(__nv_bfloat16*)(sm + SM_BH + off) = h;
            *(__nv_bfloat16*)(sm + SM_BL + off) = l;
        }
    }
    __syncthreads();

    int mrow0 = (w & 3) * 32;      // warp row base within CTA tile
    int ncol0 = (w >> 2) * 64;     // warp col base

    float acc[8][2][4];            // [n-tile][m-tile][frag]
    #pragma unroll
    for (int nt = 0; nt < 8; nt++)
        #pragma unroll
        for (int mt = 0; mt < 2; mt++)
            #pragma unroll
            for (int q = 0; q < 4; q++) acc[nt][mt][q] = 0.f;

    // per-lane invariants for ldmatrix addressing
    int a_row_off = ((lane >> 3) & 1) * 8 + (lane & 7);   // row within 16-row frag
    int a_chsel   = lane >> 4;                            // 0/1 -> k chunk select
    int b_row     = lane & 7;                             // row within 8-row frag
    int b_chsel   = (lane >> 3) & 1;

    const uint32_t apl[3] = {SM_AH, SM_AH, SM_AL};
    const uint32_t bpl[3] = {SM_BH, SM_BL, SM_BH};

    #pragma unroll
    for (int p = 0; p < 3; p++) {
        uint32_t ab = smb + apl[p];
        uint32_t bb = smb + bpl[p];
        #pragma unroll
        for (int ks = 0; ks < 8; ks++) {
            // A fragments for both m-tiles (m16k16 each)
            uint32_t a[2][4];
            #pragma unroll
            for (int mt = 0; mt < 2; mt++) {
                int row = mrow0 + mt * 16 + a_row_off;
                int ch  = ks * 2 + a_chsel;
                uint32_t addr = ab + (uint32_t)(row * 256 + ((ch ^ (row & 7)) << 4));
                asm volatile(
                    "ldmatrix.sync.aligned.m8n8.x4.shared.b16 {%0,%1,%2,%3}, [%4];"
                    : "=r"(a[mt][0]), "=r"(a[mt][1]), "=r"(a[mt][2]), "=r"(a[mt][3])
                    : "r"(addr));
            }
            #pragma unroll
            for (int nt = 0; nt < 8; nt++) {
                int row = ncol0 + nt * 8 + b_row;
                int ch  = ks * 2 + b_chsel;
                uint32_t addr = bb + (uint32_t)(row * 256 + ((ch ^ (row & 7)) << 4));
                uint32_t bfr[2];
                asm volatile(
                    "ldmatrix.sync.aligned.m8n8.x2.shared.b16 {%0,%1}, [%2];"
                    : "=r"(bfr[0]), "=r"(bfr[1]) : "r"(addr));
                #pragma unroll
                for (int mt = 0; mt < 2; mt++) {
                    asm volatile(
                        "mma.sync.aligned.m16n8k16.row.col.f32.bf16.bf16.f32 "
                        "{%0,%1,%2,%3}, {%4,%5,%6,%7}, {%8,%9}, {%0,%1,%2,%3};"
                        : "+f"(acc[nt][mt][0]), "+f"(acc[nt][mt][1]),
                          "+f"(acc[nt][mt][2]), "+f"(acc[nt][mt][3])
                        : "r"(a[mt][0]), "r"(a[mt][1]), "r"(a[mt][2]), "r"(a[mt][3]),
                          "r"(bfr[0]), "r"(bfr[1]));
                }
            }
        }
    }

    // ---- epilogue: scale by dinv[row], store float2 pairs ----
    {
        int crow = lane >> 2;          // 0..7
        int ccol = (lane & 3) * 2;
        #pragma unroll
        for (int mt = 0; mt < 2; mt++) {
            int r_lo = row0 + mrow0 + mt * 16 + crow;
            int r_hi = r_lo + 8;
            float d_lo = (r_lo < n) ? g_dinv[r_lo] : 0.f;
            float d_hi = (r_hi < n) ? g_dinv[r_hi] : 0.f;
            #pragma unroll
            for (int nt = 0; nt < 8; nt++) {
                int col = ncol0 + nt * 8 + ccol;
                if (r_lo < n) {
                    float2 o; o.x = acc[nt][mt][0] * d_lo; o.y = acc[nt][mt][1] * d_lo;
                    *(float2*)&g_hs[r_lo * NF + col] = o;
                }
                if (r_hi < n) {
                    float2 o; o.x = acc[nt][mt][2] * d_hi; o.y = acc[nt][mt][3] * d_hi;
                    *(float2*)&g_hs[r_hi * NF + col] = o;
                }
            }
        }
    }
}

// ---------------- Aggregation: warp per dst node ----------------
__global__ void k_agg(const float* __restrict__ bias, int n, int do_relu) {
    int gw = (blockIdx.x * blockDim.x + threadIdx.x) >> 5;
    int lane = threadIdx.x & 31;
    if (gw >= n) return;

    const float4* hs4 = (const float4*)g_hs;
    float4 acc = hs4[gw * 32 + lane];

    int s = g_rowptr[gw];
    int e = g_rowptr[gw + 1];
    for (int b = s; b < e; b += 32) {
        int idx = (b + lane < e) ? g_col[b + lane] : 0;
        int cnt = min(32, e - b);
        int j = 0;
        for (; j + 4 <= cnt; j += 4) {
            int s0 = __shfl_sync(0xffffffffu, idx, j);
            int s1 = __shfl_sync(0xffffffffu, idx, j + 1);
            int s2 = __shfl_sync(0xffffffffu, idx, j + 2);
            int s3 = __shfl_sync(0xffffffffu, idx, j + 3);
            float4 v0 = hs4[s0 * 32 + lane];
            float4 v1 = hs4[s1 * 32 + lane];
            float4 v2 = hs4[s2 * 32 + lane];
            float4 v3 = hs4[s3 * 32 + lane];
            acc.x += (v0.x + v1.x) + (v2.x + v3.x);
            acc.y += (v0.y + v1.y) + (v2.y + v3.y);
            acc.z += (v0.z + v1.z) + (v2.z + v3.z);
            acc.w += (v0.w + v1.w) + (v2.w + v3.w);
        }
        for (; j < cnt; j++) {
            int sj = __shfl_sync(0xffffffffu, idx, j);
            float4 v = hs4[sj * 32 + lane];
            acc.x += v.x; acc.y += v.y; acc.z += v.z; acc.w += v.w;
        }
    }

    float di = g_dinv[gw];
    float4 bb = ((const float4*)bias)[lane];
    float4 o;
    o.x = di * acc.x + bb.x;
    o.y = di * acc.y + bb.y;
    o.z = di * acc.z + bb.z;
    o.w = di * acc.w + bb.w;
    if (do_relu) {
        o.x = fmaxf(o.x, 0.f); o.y = fmaxf(o.y, 0.f);
        o.z = fmaxf(o.z, 0.f); o.w = fmaxf(o.w, 0.f);
    }
    ((float4*)g_a)[gw * 32 + lane] = o;
}

// ---------------- Final: out = log_softmax(A @ Wout + bout) ----------------
__global__ void k_final(const float* __restrict__ Wout,
                        const float* __restrict__ bout,
                        float* __restrict__ out, int n) {
    __shared__ float Ws[NF * NC];
    __shared__ float bs[NC];
    int t = threadIdx.x;
    for (int i = t; i < NF * NC; i += blockDim.x) Ws[i] = Wout[i];
    if (t < NC) bs[t] = bout[t];
    __syncthreads();

    int row = blockIdx.x * blockDim.x + t;
    if (row >= n) return;

    float acc[NC];
    #pragma unroll
    for (int c = 0; c < NC; c++) acc[c] = bs[c];

    const float4* A4  = (const float4*)g_a;
    const float4* Ws4 = (const float4*)Ws;
    for (int k4 = 0; k4 < NF / 4; k4++) {
        float4 xv = A4[row * 32 + k4];
        #pragma unroll
        for (int c4 = 0; c4 < NC / 4; c4++) {
            float4 w0 = Ws4[(k4 * 4 + 0) * (NC / 4) + c4];
            float4 w1 = Ws4[(k4 * 4 + 1) * (NC / 4) + c4];
            float4 w2 = Ws4[(k4 * 4 + 2) * (NC / 4) + c4];
            float4 w3 = Ws4[(k4 * 4 + 3) * (NC / 4) + c4];
            acc[c4 * 4 + 0] += xv.x * w0.x + xv.y * w1.x + xv.z * w2.x + xv.w * w3.x;
            acc[c4 * 4 + 1] += xv.x * w0.y + xv.y * w1.y + xv.z * w2.y + xv.w * w3.y;
            acc[c4 * 4 + 2] += xv.x * w0.z + xv.y * w1.z + xv.z * w2.z + xv.w * w3.z;
            acc[c4 * 4 + 3] += xv.x * w0.w + xv.y * w1.w + xv.z * w2.w + xv.w * w3.w;
        }
    }

    float m = acc[0];
    #pragma unroll
    for (int c = 1; c < NC; c++) m = fmaxf(m, acc[c]);
    float ssum = 0.f;
    #pragma unroll
    for (int c = 0; c < NC; c++) ssum += __expf(acc[c] - m);
    float ls = m + __logf(ssum);
    #pragma unroll
    for (int c = 0; c < NC; c++) out[row * NC + c] = acc[c] - ls;
}

// ---------------- launch ----------------
extern "C" void kernel_launch(void* const* d_in, const int* in_sizes, int n_in,
                              void* d_out, int out_size) {
    const float* x    = (const float*)d_in[0];
    const void*  ei   = d_in[1];
    const float* Win  = (const float*)d_in[2];
    const float* bin  = (const float*)d_in[3];
    const float* W1   = (const float*)d_in[4];
    const float* b1   = (const float*)d_in[5];
    const float* Wout = (const float*)d_in[6];
    const float* bout = (const float*)d_in[7];
    float* out = (float*)d_out;

    int n = in_sizes[0] / NF;       // 50000
    int E = in_sizes[1] / 2;        // 800000
    int nb = (n + SCAN_TILE - 1) / SCAN_TILE;

    cudaFuncSetAttribute(k_gemm_mma, cudaFuncAttributeMaxDynamicSharedMemorySize,
                         SM_TOTAL);

    // CSR build (every call; no caching allowed)
    k_zero   <<<(n + 255) / 256, 256>>>(n);
    k_detect <<<1, 32>>>((const unsigned int*)ei);
    k_decode <<<(E + 255) / 256, 256>>>(ei, E);
    k_scan1  <<<nb, SCAN_TILE>>>(n);
    k_scan2  <<<1, 64>>>(nb, n);
    k_scan3  <<<nb, SCAN_TILE>>>(n);
    k_scatter<<<(E + 255) / 256, 256>>>(E);

    int gemm_blocks = (n + 127) / 128;     // 391
    int agg_blocks  = (n * 32 + 255) / 256;

    // layer 1
    k_gemm_mma<<<gemm_blocks, 256, SM_TOTAL>>>(x, Win, 0, n);
    k_agg     <<<agg_blocks, 256>>>(bin, n, 0);
    // layer 2
    k_gemm_mma<<<gemm_blocks, 256, SM_TOTAL>>>(nullptr, W1, 1, n);
    k_agg     <<<agg_blocks, 256>>>(b1, n, 1);
    // output
    k_final<<<(n + 255) / 256, 256>>>(Wout, bout, out, n);
}

// round 5
// speedup vs baseline: 1.2285x; 1.2285x over previous
#include <cuda_runtime.h>
#include <cuda_bf16.h>
#include <cuda_fp16.h>
#include <cstdint>

#define N_NODES_MAX 50000
#define E_MAX       800000
#define NF          128
#define NC          40
#define SCAN_TILE   1024
#define NB_MAX      ((N_NODES_MAX + SCAN_TILE - 1) / SCAN_TILE)   // 49

// ---------------- scratch (static device globals; no allocation) ----------------
__device__ int   g_dst[E_MAX];
__device__ int   g_pos[E_MAX];
__device__ int   g_col[E_MAX];
__device__ int   g_deg[N_NODES_MAX];
__device__ int   g_rowptr[N_NODES_MAX + 1];
__device__ int   g_bsum[NB_MAX];
__device__ int   g_boff[NB_MAX];
__device__ float g_dinv[N_NODES_MAX];
__device__ __align__(16) __half2 g_hs16[N_NODES_MAX * 64];   // dinv*(X@W), fp16
__device__ __align__(16) float   g_a[N_NODES_MAX * NF];      // agg output, fp32
__device__ __align__(16) __nv_bfloat16 g_WhT[NF * NF];       // W^T hi plane
__device__ __align__(16) __nv_bfloat16 g_WlT[NF * NF];       // W^T lo plane
__device__ int   g_flag64;

// ---------------- CSR build ----------------
__global__ void k_zero(int n) {
    int i = blockIdx.x * blockDim.x + threadIdx.x;
    if (i < n) g_deg[i] = 0;
}

__global__ void k_detect(const unsigned int* __restrict__ ei_words) {
    unsigned v = ei_words[2 * threadIdx.x + 1];
    unsigned mask = __ballot_sync(0xffffffffu, v != 0u);
    if (threadIdx.x == 0) g_flag64 = (mask == 0u) ? 1 : 0;
}

// Histogram destination degrees; remember within-bucket slot.
__global__ void k_decode(const void* __restrict__ ei, int E) {
    int e = blockIdx.x * blockDim.x + threadIdx.x;
    if (e >= E) return;
    int d;
    if (g_flag64) d = (int)((const long long*)ei)[E + e];
    else          d = ((const int*)ei)[E + e];
    g_dst[e] = d;
    g_pos[e] = atomicAdd(&g_deg[d], 1);
}

__global__ void k_scan1(int n) {
    __shared__ int warpsum[32];
    int b = blockIdx.x;
    int i = b * SCAN_TILE + threadIdx.x;
    int lane = threadIdx.x & 31;
    int w    = threadIdx.x >> 5;
    int v = (i < n) ? g_deg[i] : 0;

    int incl = v;
    #pragma unroll
    for (int off = 1; off < 32; off <<= 1) {
        int t = __shfl_up_sync(0xffffffffu, incl, off);
        if (lane >= off) incl += t;
    }
    if (lane == 31) warpsum[w] = incl;
    __syncthreads();
    if (w == 0) {
        int s = warpsum[lane];
        #pragma unroll
        for (int off = 1; off < 32; off <<= 1) {
            int t = __shfl_up_sync(0xffffffffu, s, off);
            if (lane >= off) s += t;
        }
        warpsum[lane] = s;
    }
    __syncthreads();
    int excl = incl - v + (w > 0 ? warpsum[w - 1] : 0);
    if (i < n) {
        g_rowptr[i] = excl;
        g_dinv[i]   = rsqrtf(1.0f + (float)v);
    }
    if (threadIdx.x == 0) g_bsum[b] = warpsum[31];
}

__global__ void k_scan2(int nb, int n) {
    __shared__ int sh[64];
    int t = threadIdx.x;
    int v = (t < nb) ? g_bsum[t] : 0;
    sh[t] = v;
    __syncthreads();
    #pragma unroll
    for (int off = 1; off < 64; off <<= 1) {
        int a = (t >= off) ? sh[t - off] : 0;
        __syncthreads();
        sh[t] += a;
        __syncthreads();
    }
    if (t < nb) g_boff[t] = sh[t] - v;
    if (t == 63) g_rowptr[n] = sh[63];
}

__global__ void k_scan3(int n) {
    int i = blockIdx.x * SCAN_TILE + threadIdx.x;
    if (i < n) g_rowptr[i] += g_boff[blockIdx.x];
}

// Atomic-free scatter; src read directly from edge_index.
__global__ void k_scatter(const void* __restrict__ ei, int E) {
    int e = blockIdx.x * blockDim.x + threadIdx.x;
    if (e >= E) return;
    int s;
    if (g_flag64) s = (int)((const long long*)ei)[e];
    else          s = ((const int*)ei)[e];
    int d = g_dst[e];
    g_col[g_rowptr[d] + g_pos[e]] = s;
}

// ---------------- W split: W[k][n] fp32 -> W^T[n][k] bf16 hi/lo planes ----------------
__global__ void k_wsplit(const float* __restrict__ W) {
    int i = blockIdx.x * blockDim.x + threadIdx.x;   // 16384
    int k  = i >> 7;
    int nn = i & 127;
    float v = W[i];
    __nv_bfloat16 h = __float2bfloat16_rn(v);
    __nv_bfloat16 l = __float2bfloat16_rn(v - __bfloat162float(h));
    g_WhT[nn * NF + k] = h;
    g_WlT[nn * NF + k] = l;
}

// ---------------- HMMA GEMM: hs16[row] = fp16( dinv[row] * (X[row] @ W) ) ----------------
// Split-bf16, fp32 accum: D = Xh Wh + Xh Wl + Xl Wh.
// CTA tile 128x128; K staged in 2 halves of 64 -> 64 KB smem, 2 CTAs/SM.
// 8 warps (4x2): warp tile 32 rows x 64 cols.
// smem tile: 128 rows x 64 bf16 = 128 B/row; 16B-chunk XOR swizzle by (row&7).

#define TS       16384
#define SM_AH    0
#define SM_AL    16384
#define SM_BH    32768
#define SM_BL    49152
#define SM_TOTAL 65536

__device__ __forceinline__ uint32_t sm_u32(const void* p) {
    uint32_t r;
    asm("{ .reg .u64 t; cvta.to.shared.u64 t, %1; cvt.u32.u64 %0, t; }"
        : "=r"(r) : "l"(p));
    return r;
}

__global__ void __launch_bounds__(256, 2)
k_gemm_mma(const float* __restrict__ Xext, int use_internal, int n) {
    extern __shared__ char sm[];
    uint32_t smb = sm_u32(sm);
    const float* X = use_internal ? (const float*)g_a : Xext;

    int t = threadIdx.x;
    int lane = t & 31;
    int w = t >> 5;
    int row0 = blockIdx.x * 128;
    int mrow0 = (w & 3) * 32;
    int ncol0 = (w >> 2) * 64;

    float acc[8][2][4];
    #pragma unroll
    for (int nt = 0; nt < 8; nt++)
        #pragma unroll
        for (int mt = 0; mt < 2; mt++)
            #pragma unroll
            for (int q = 0; q < 4; q++) acc[nt][mt][q] = 0.f;

    int a_row_off = ((lane >> 3) & 1) * 8 + (lane & 7);
    int a_chsel   = lane >> 4;
    int b_row     = lane & 7;
    int b_chsel   = (lane >> 3) & 1;

    const uint32_t apl[3] = {SM_AH, SM_AH, SM_AL};
    const uint32_t bpl[3] = {SM_BH, SM_BL, SM_BH};

    #pragma unroll
    for (int hf = 0; hf < 2; hf++) {
        if (hf) __syncthreads();   // protect smem reuse between halves
        // ---- stage A: X cols [hf*64, hf*64+64), hi/lo bf16 swizzled ----
        {
            const float4* X4 = (const float4*)X;
            for (int i = t; i < 128 * 16; i += 256) {
                int r  = i >> 4;
                int c4 = i & 15;
                int gr = row0 + r;
                float4 v = (gr < n) ? X4[gr * 32 + hf * 16 + c4]
                                    : make_float4(0.f, 0.f, 0.f, 0.f);
                int k0 = c4 * 4;
                uint32_t off = (uint32_t)(r * 128 +
                               (((k0 >> 3) ^ (r & 7)) << 4) + (k0 & 7) * 2);
                float f[4] = {v.x, v.y, v.z, v.w};
                __nv_bfloat16 h0 = __float2bfloat16_rn(f[0]);
                __nv_bfloat16 h1 = __float2bfloat16_rn(f[1]);
                __nv_bfloat16 h2 = __float2bfloat16_rn(f[2]);
                __nv_bfloat16 h3 = __float2bfloat16_rn(f[3]);
                __nv_bfloat162 h01, h23, l01, l23;
                h01.x = h0; h01.y = h1; h23.x = h2; h23.y = h3;
                l01.x = __float2bfloat16_rn(f[0] - __bfloat162float(h0));
                l01.y = __float2bfloat16_rn(f[1] - __bfloat162float(h1));
                l23.x = __float2bfloat16_rn(f[2] - __bfloat162float(h2));
                l23.y = __float2bfloat16_rn(f[3] - __bfloat162float(h3));
                *(__nv_bfloat162*)(sm + SM_AH + off)     = h01;
                *(__nv_bfloat162*)(sm + SM_AH + off + 4) = h23;
                *(__nv_bfloat162*)(sm + SM_AL + off)     = l01;
                *(__nv_bfloat162*)(sm + SM_AL + off + 4) = l23;
            }
        }
        // ---- stage B: W^T rows 0..127, k [hf*64, +64), 16B chunk copies ----
        {
            const uint4* Wh4 = (const uint4*)g_WhT;
            const uint4* Wl4 = (const uint4*)g_WlT;
            for (int i = t; i < 128 * 8; i += 256) {
                int nn = i >> 3;
                int ch = i & 7;
                uint4 vh = Wh4[nn * 16 + hf * 8 + ch];
                uint4 vl = Wl4[nn * 16 + hf * 8 + ch];
                uint32_t off = (uint32_t)(nn * 128 + ((ch ^ (nn & 7)) << 4));
                *(uint4*)(sm + SM_BH + off) = vh;
                *(uint4*)(sm + SM_BL + off) = vl;
            }
        }
        __syncthreads();

        #pragma unroll
        for (int p = 0; p < 3; p++) {
            uint32_t ab = smb + apl[p];
            uint32_t bb = smb + bpl[p];
            #pragma unroll
            for (int ks = 0; ks < 4; ks++) {
                uint32_t a[2][4];
                #pragma unroll
                for (int mt = 0; mt < 2; mt++) {
                    int row = mrow0 + mt * 16 + a_row_off;
                    int ch  = ks * 2 + a_chsel;
                    uint32_t addr = ab + (uint32_t)(row * 128 + ((ch ^ (row & 7)) << 4));
                    asm volatile(
                        "ldmatrix.sync.aligned.m8n8.x4.shared.b16 {%0,%1,%2,%3}, [%4];"
                        : "=r"(a[mt][0]), "=r"(a[mt][1]), "=r"(a[mt][2]), "=r"(a[mt][3])
                        : "r"(addr));
                }
                #pragma unroll
                for (int nt = 0; nt < 8; nt++) {
                    int row = ncol0 + nt * 8 + b_row;
                    int ch  = ks * 2 + b_chsel;
                    uint32_t addr = bb + (uint32_t)(row * 128 + ((ch ^ (row & 7)) << 4));
                    uint32_t bfr[2];
                    asm volatile(
                        "ldmatrix.sync.aligned.m8n8.x2.shared.b16 {%0,%1}, [%2];"
                        : "=r"(bfr[0]), "=r"(bfr[1]) : "r"(addr));
                    #pragma unroll
                    for (int mt = 0; mt < 2; mt++) {
                        asm volatile(
                            "mma.sync.aligned.m16n8k16.row.col.f32.bf16.bf16.f32 "
                            "{%0,%1,%2,%3}, {%4,%5,%6,%7}, {%8,%9}, {%0,%1,%2,%3};"
                            : "+f"(acc[nt][mt][0]), "+f"(acc[nt][mt][1]),
                              "+f"(acc[nt][mt][2]), "+f"(acc[nt][mt][3])
                            : "r"(a[mt][0]), "r"(a[mt][1]), "r"(a[mt][2]), "r"(a[mt][3]),
                              "r"(bfr[0]), "r"(bfr[1]));
                    }
                }
            }
        }
    }

    // ---- epilogue: scale by dinv[row], store fp16 pairs ----
    {
        int crow = lane >> 2;
        int ccol = (lane & 3) * 2;
        #pragma unroll
        for (int mt = 0; mt < 2; mt++) {
            int r_lo = row0 + mrow0 + mt * 16 + crow;
            int r_hi = r_lo + 8;
            float d_lo = (r_lo < n) ? g_dinv[r_lo] : 0.f;
            float d_hi = (r_hi < n) ? g_dinv[r_hi] : 0.f;
            #pragma unroll
            for (int nt = 0; nt < 8; nt++) {
                int col = ncol0 + nt * 8 + ccol;
                if (r_lo < n)
                    g_hs16[r_lo * 64 + (col >> 1)] =
                        __floats2half2_rn(acc[nt][mt][0] * d_lo, acc[nt][mt][1] * d_lo);
                if (r_hi < n)
                    g_hs16[r_hi * 64 + (col >> 1)] =
                        __floats2half2_rn(acc[nt][mt][2] * d_hi, acc[nt][mt][3] * d_hi);
            }
        }
    }
}

// ---------------- Aggregation: warp per dst node; fp16 gather, fp32 accum ----------------
__global__ void k_agg(const float* __restrict__ bias, int n, int do_relu) {
    int gw = (blockIdx.x * blockDim.x + threadIdx.x) >> 5;
    int lane = threadIdx.x & 31;
    if (gw >= n) return;

    const uint2* hp = (const uint2*)g_hs16;   // 8 B = 4 halves per lane

    float4 acc;
    {
        uint2 u = hp[gw * 32 + lane];
        float2 f0 = __half22float2(*(__half2*)&u.x);
        float2 f1 = __half22float2(*(__half2*)&u.y);
        acc.x = f0.x; acc.y = f0.y; acc.z = f1.x; acc.w = f1.y;
    }

    int s = g_rowptr[gw];
    int e = g_rowptr[gw + 1];
    for (int b = s; b < e; b += 32) {
        int idx = (b + lane < e) ? g_col[b + lane] : 0;
        int cnt = min(32, e - b);
        int j = 0;
        for (; j + 4 <= cnt; j += 4) {
            int s0 = __shfl_sync(0xffffffffu, idx, j);
            int s1 = __shfl_sync(0xffffffffu, idx, j + 1);
            int s2 = __shfl_sync(0xffffffffu, idx, j + 2);
            int s3 = __shfl_sync(0xffffffffu, idx, j + 3);
            uint2 u0 = hp[s0 * 32 + lane];
            uint2 u1 = hp[s1 * 32 + lane];
            uint2 u2 = hp[s2 * 32 + lane];
            uint2 u3 = hp[s3 * 32 + lane];
            float2 a0 = __half22float2(*(__half2*)&u0.x), b0 = __half22float2(*(__half2*)&u0.y);
            float2 a1 = __half22float2(*(__half2*)&u1.x), b1 = __half22float2(*(__half2*)&u1.y);
            float2 a2 = __half22float2(*(__half2*)&u2.x), b2 = __half22float2(*(__half2*)&u2.y);
            float2 a3 = __half22float2(*(__half2*)&u3.x), b3 = __half22float2(*(__half2*)&u3.y);
            acc.x += (a0.x + a1.x) + (a2.x + a3.x);
            acc.y += (a0.y + a1.y) + (a2.y + a3.y);
            acc.z += (b0.x + b1.x) + (b2.x + b3.x);
            acc.w += (b0.y + b1.y) + (b2.y + b3.y);
        }
        for (; j < cnt; j++) {
            int sj = __shfl_sync(0xffffffffu, idx, j);
            uint2 u = hp[sj * 32 + lane];
            float2 a = __half22float2(*(__half2*)&u.x);
            float2 bq = __half22float2(*(__half2*)&u.y);
            acc.x += a.x; acc.y += a.y; acc.z += bq.x; acc.w += bq.y;
        }
    }

    float di = g_dinv[gw];
    float4 bb = ((const float4*)bias)[lane];
    float4 o;
    o.x = di * acc.x + bb.x;
    o.y = di * acc.y + bb.y;
    o.z = di * acc.z + bb.z;
    o.w = di * acc.w + bb.w;
    if (do_relu) {
        o.x = fmaxf(o.x, 0.f); o.y = fmaxf(o.y, 0.f);
        o.z = fmaxf(o.z, 0.f); o.w = fmaxf(o.w, 0.f);
    }
    ((float4*)g_a)[gw * 32 + lane] = o;
}

// ---------------- Final: out = log_softmax(A @ Wout + bout) ----------------
__global__ void k_final(const float* __restrict__ Wout,
                        const float* __restrict__ bout,
                        float* __restrict__ out, int n) {
    __shared__ float Ws[NF * NC];
    __shared__ float bs[NC];
    int t = threadIdx.x;
    for (int i = t; i < NF * NC; i += blockDim.x) Ws[i] = Wout[i];
    if (t < NC) bs[t] = bout[t];
    __syncthreads();

    int row = blockIdx.x * blockDim.x + t;
    if (row >= n) return;

    float acc[NC];
    #pragma unroll
    for (int c = 0; c < NC; c++) acc[c] = bs[c];

    const float4* A4  = (const float4*)g_a;
    const float4* Ws4 = (const float4*)Ws;
    for (int k4 = 0; k4 < NF / 4; k4++) {
        float4 xv = A4[row * 32 + k4];
        #pragma unroll
        for (int c4 = 0; c4 < NC / 4; c4++) {
            float4 w0 = Ws4[(k4 * 4 + 0) * (NC / 4) + c4];
            float4 w1 = Ws4[(k4 * 4 + 1) * (NC / 4) + c4];
            float4 w2 = Ws4[(k4 * 4 + 2) * (NC / 4) + c4];
            float4 w3 = Ws4[(k4 * 4 + 3) * (NC / 4) + c4];
            acc[c4 * 4 + 0] += xv.x * w0.x + xv.y * w1.x + xv.z * w2.x + xv.w * w3.x;
            acc[c4 * 4 + 1] += xv.x * w0.y + xv.y * w1.y + xv.z * w2.y + xv.w * w3.y;
            acc[c4 * 4 + 2] += xv.x * w0.z + xv.y * w1.z + xv.z * w2.z + xv.w * w3.z;
            acc[c4 * 4 + 3] += xv.x * w0.w + xv.y * w1.w + xv.z * w2.w + xv.w * w3.w;
        }
    }

    float m = acc[0];
    #pragma unroll
    for (int c = 1; c < NC; c++) m = fmaxf(m, acc[c]);
    float ssum = 0.f;
    #pragma unroll
    for (int c = 0; c < NC; c++) ssum += __expf(acc[c] - m);
    float ls = m + __logf(ssum);
    #pragma unroll
    for (int c = 0; c < NC; c++) out[row * NC + c] = acc[c] - ls;
}

// ---------------- launch ----------------
extern "C" void kernel_launch(void* const* d_in, const int* in_sizes, int n_in,
                              void* d_out, int out_size) {
    const float* x    = (const float*)d_in[0];
    const void*  ei   = d_in[1];
    const float* Win  = (const float*)d_in[2];
    const float* bin  = (const float*)d_in[3];
    const float* W1   = (const float*)d_in[4];
    const float* b1   = (const float*)d_in[5];
    const float* Wout = (const float*)d_in[6];
    const float* bout = (const float*)d_in[7];
    float* out = (float*)d_out;

    int n = in_sizes[0] / NF;       // 50000
    int E = in_sizes[1] / 2;        // 800000
    int nb = (n + SCAN_TILE - 1) / SCAN_TILE;

    cudaFuncSetAttribute(k_gemm_mma, cudaFuncAttributeMaxDynamicSharedMemorySize,
                         SM_TOTAL);

    // CSR build (every call; no caching allowed)
    k_zero   <<<(n + 255) / 256, 256>>>(n);
    k_detect <<<1, 32>>>((const unsigned int*)ei);
    k_decode <<<(E + 255) / 256, 256>>>(ei, E);
    k_scan1  <<<nb, SCAN_TILE>>>(n);
    k_scan2  <<<1, 64>>>(nb, n);
    k_scan3  <<<nb, SCAN_TILE>>>(n);
    k_scatter<<<(E + 255) / 256, 256>>>(ei, E);

    int gemm_blocks = (n + 127) / 128;     // 391
    int agg_blocks  = (n * 32 + 255) / 256;

    // layer 1
    k_wsplit  <<<64, 256>>>(Win);
    k_gemm_mma<<<gemm_blocks, 256, SM_TOTAL>>>(x, 0, n);
    k_agg     <<<agg_blocks, 256>>>(bin, n, 0);
    // layer 2
    k_wsplit  <<<64, 256>>>(W1);
    k_gemm_mma<<<gemm_blocks, 256, SM_TOTAL>>>(nullptr, 1, n);
    k_agg     <<<agg_blocks, 256>>>(b1, n, 1);
    // output
    k_final<<<(n + 255) / 256, 256>>>(Wout, bout, out, n);
}

// round 6
// speedup vs baseline: 1.4109x; 1.1485x over previous
#include <cuda_runtime.h>
#include <cuda_bf16.h>
#include <cuda_fp16.h>
#include <cstdint>

#define N_NODES_MAX 50000
#define E_MAX       800000
#define NF          128
#define NC          40
#define SCAN_TILE   1024
#define NB_MAX      ((N_NODES_MAX + SCAN_TILE - 1) / SCAN_TILE)   // 49

// ---------------- scratch (static device globals; no allocation) ----------------
__device__ int   g_dst[E_MAX];
__device__ int   g_pos[E_MAX];
__device__ int   g_col[E_MAX];
__device__ int   g_deg[N_NODES_MAX];
__device__ int   g_rowptr[N_NODES_MAX + 1];
__device__ int   g_bsum[NB_MAX];
__device__ int   g_boff[NB_MAX];
__device__ float g_dinv[N_NODES_MAX];
__device__ __align__(16) __half2        g_hs16[N_NODES_MAX * 64]; // dinv*(X@W), fp16 (gather src)
__device__ __align__(16) __half2        g_h2[N_NODES_MAX * 64];   // layer2 agg out, fp16
__device__ __align__(16) __nv_bfloat16  g_Ab[N_NODES_MAX * NF];   // layer1 agg out, bf16 (GEMM2 A)
__device__ __align__(16) __nv_bfloat16  g_WT[NF * NF];            // W^T bf16
__device__ int   g_flag64;

// ---------------- CSR build ----------------
__global__ void k_zero(int n) {
    int i = blockIdx.x * blockDim.x + threadIdx.x;
    if (i < n) g_deg[i] = 0;
}

__global__ void k_detect(const unsigned int* __restrict__ ei_words) {
    unsigned v = ei_words[2 * threadIdx.x + 1];
    unsigned mask = __ballot_sync(0xffffffffu, v != 0u);
    if (threadIdx.x == 0) g_flag64 = (mask == 0u) ? 1 : 0;
}

__global__ void k_decode(const void* __restrict__ ei, int E) {
    int e = blockIdx.x * blockDim.x + threadIdx.x;
    if (e >= E) return;
    int d;
    if (g_flag64) d = (int)((const long long*)ei)[E + e];
    else          d = ((const int*)ei)[E + e];
    g_dst[e] = d;
    g_pos[e] = atomicAdd(&g_deg[d], 1);
}

__global__ void k_scan1(int n) {
    __shared__ int warpsum[32];
    int b = blockIdx.x;
    int i = b * SCAN_TILE + threadIdx.x;
    int lane = threadIdx.x & 31;
    int w    = threadIdx.x >> 5;
    int v = (i < n) ? g_deg[i] : 0;

    int incl = v;
    #pragma unroll
    for (int off = 1; off < 32; off <<= 1) {
        int t = __shfl_up_sync(0xffffffffu, incl, off);
        if (lane >= off) incl += t;
    }
    if (lane == 31) warpsum[w] = incl;
    __syncthreads();
    if (w == 0) {
        int s = warpsum[lane];
        #pragma unroll
        for (int off = 1; off < 32; off <<= 1) {
            int t = __shfl_up_sync(0xffffffffu, s, off);
            if (lane >= off) s += t;
        }
        warpsum[lane] = s;
    }
    __syncthreads();
    int excl = incl - v + (w > 0 ? warpsum[w - 1] : 0);
    if (i < n) {
        g_rowptr[i] = excl;
        g_dinv[i]   = rsqrtf(1.0f + (float)v);
    }
    if (threadIdx.x == 0) g_bsum[b] = warpsum[31];
}

__global__ void k_scan2(int nb, int n) {
    __shared__ int sh[64];
    int t = threadIdx.x;
    int v = (t < nb) ? g_bsum[t] : 0;
    sh[t] = v;
    __syncthreads();
    #pragma unroll
    for (int off = 1; off < 64; off <<= 1) {
        int a = (t >= off) ? sh[t - off] : 0;
        __syncthreads();
        sh[t] += a;
        __syncthreads();
    }
    if (t < nb) g_boff[t] = sh[t] - v;
    if (t == 63) g_rowptr[n] = sh[63];
}

__global__ void k_scan3(int n) {
    int i = blockIdx.x * SCAN_TILE + threadIdx.x;
    if (i < n) g_rowptr[i] += g_boff[blockIdx.x];
}

__global__ void k_scatter(const void* __restrict__ ei, int E) {
    int e = blockIdx.x * blockDim.x + threadIdx.x;
    if (e >= E) return;
    int s;
    if (g_flag64) s = (int)((const long long*)ei)[e];
    else          s = ((const int*)ei)[e];
    int d = g_dst[e];
    g_col[g_rowptr[d] + g_pos[e]] = s;
}

// ---------------- W split: W[k][n] fp32 -> W^T[n][k] bf16 ----------------
__global__ void k_wsplit(const float* __restrict__ W) {
    int i = blockIdx.x * blockDim.x + threadIdx.x;   // 16384
    int k  = i >> 7;
    int nn = i & 127;
    g_WT[nn * NF + k] = __float2bfloat16_rn(W[i]);
}

// ---------------- HMMA GEMM: hs16[row] = fp16( dinv[row] * (X[row] @ W) ) ----------------
// Pure bf16, fp32 accum, single pass. CTA tile 128x128, full K=128 staged once.
// smem: A tile 32KB + B tile 32KB (256 B/row, 16B-chunk XOR swizzle by row&7).

#define SM_A     0
#define SM_B     32768
#define SM_TOTAL 65536

__device__ __forceinline__ uint32_t sm_u32(const void* p) {
    uint32_t r;
    asm("{ .reg .u64 t; cvta.to.shared.u64 t, %1; cvt.u32.u64 %0, t; }"
        : "=r"(r) : "l"(p));
    return r;
}

__global__ void __launch_bounds__(256, 2)
k_gemm_mma(const float* __restrict__ Xext, int use_internal, int n) {
    extern __shared__ char sm[];
    uint32_t smb = sm_u32(sm);

    int t = threadIdx.x;
    int lane = t & 31;
    int w = t >> 5;
    int row0 = blockIdx.x * 128;
    int mrow0 = (w & 3) * 32;
    int ncol0 = (w >> 2) * 64;

    // ---- stage A: 128 rows x 128 k of bf16, swizzled 256 B/row ----
    if (use_internal) {
        const uint4* Ab4 = (const uint4*)g_Ab;      // 16 chunks of 16B per row
        for (int i = t; i < 128 * 16; i += 256) {
            int r  = i >> 4;
            int ch = i & 15;
            int gr = row0 + r;
            uint4 v = (gr < n) ? Ab4[gr * 16 + ch] : make_uint4(0, 0, 0, 0);
            uint32_t off = (uint32_t)(r * 256 + ((ch ^ (r & 7)) << 4));
            *(uint4*)(sm + SM_A + off) = v;
        }
    } else {
        const float4* X4 = (const float4*)Xext;
        for (int i = t; i < 128 * 32; i += 256) {
            int r  = i >> 5;
            int c4 = i & 31;
            int gr = row0 + r;
            float4 v = (gr < n) ? X4[gr * 32 + c4]
                                : make_float4(0.f, 0.f, 0.f, 0.f);
            int k0 = c4 * 4;
            uint32_t off = (uint32_t)(r * 256 +
                           (((k0 >> 3) ^ (r & 7)) << 4) + (k0 & 7) * 2);
            __nv_bfloat162 h01, h23;
            h01.x = __float2bfloat16_rn(v.x); h01.y = __float2bfloat16_rn(v.y);
            h23.x = __float2bfloat16_rn(v.z); h23.y = __float2bfloat16_rn(v.w);
            *(__nv_bfloat162*)(sm + SM_A + off)     = h01;
            *(__nv_bfloat162*)(sm + SM_A + off + 4) = h23;
        }
    }
    // ---- stage B: W^T rows 0..127, 16 chunks each ----
    {
        const uint4* Wt4 = (const uint4*)g_WT;
        for (int i = t; i < 128 * 16; i += 256) {
            int nn = i >> 4;
            int ch = i & 15;
            uint4 v = Wt4[nn * 16 + ch];
            uint32_t off = (uint32_t)(nn * 256 + ((ch ^ (nn & 7)) << 4));
            *(uint4*)(sm + SM_B + off) = v;
        }
    }
    __syncthreads();

    float acc[8][2][4];
    #pragma unroll
    for (int nt = 0; nt < 8; nt++)
        #pragma unroll
        for (int mt = 0; mt < 2; mt++)
            #pragma unroll
            for (int q = 0; q < 4; q++) acc[nt][mt][q] = 0.f;

    int a_row_off = ((lane >> 3) & 1) * 8 + (lane & 7);
    int a_chsel   = lane >> 4;
    int b_row     = lane & 7;
    int b_chsel   = (lane >> 3) & 1;

    #pragma unroll
    for (int ks = 0; ks < 8; ks++) {
        uint32_t a[2][4];
        #pragma unroll
        for (int mt = 0; mt < 2; mt++) {
            int row = mrow0 + mt * 16 + a_row_off;
            int ch  = ks * 2 + a_chsel;
            uint32_t addr = smb + SM_A + (uint32_t)(row * 256 + ((ch ^ (row & 7)) << 4));
            asm volatile(
                "ldmatrix.sync.aligned.m8n8.x4.shared.b16 {%0,%1,%2,%3}, [%4];"
                : "=r"(a[mt][0]), "=r"(a[mt][1]), "=r"(a[mt][2]), "=r"(a[mt][3])
                : "r"(addr));
        }
        #pragma unroll
        for (int nt = 0; nt < 8; nt++) {
            int row = ncol0 + nt * 8 + b_row;
            int ch  = ks * 2 + b_chsel;
            uint32_t addr = smb + SM_B + (uint32_t)(row * 256 + ((ch ^ (row & 7)) << 4));
            uint32_t bfr[2];
            asm volatile(
                "ldmatrix.sync.aligned.m8n8.x2.shared.b16 {%0,%1}, [%2];"
                : "=r"(bfr[0]), "=r"(bfr[1]) : "r"(addr));
            #pragma unroll
            for (int mt = 0; mt < 2; mt++) {
                asm volatile(
                    "mma.sync.aligned.m16n8k16.row.col.f32.bf16.bf16.f32 "
                    "{%0,%1,%2,%3}, {%4,%5,%6,%7}, {%8,%9}, {%0,%1,%2,%3};"
                    : "+f"(acc[nt][mt][0]), "+f"(acc[nt][mt][1]),
                      "+f"(acc[nt][mt][2]), "+f"(acc[nt][mt][3])
                    : "r"(a[mt][0]), "r"(a[mt][1]), "r"(a[mt][2]), "r"(a[mt][3]),
                      "r"(bfr[0]), "r"(bfr[1]));
            }
        }
    }

    // ---- epilogue: scale by dinv[row], store fp16 pairs ----
    {
        int crow = lane >> 2;
        int ccol = (lane & 3) * 2;
        #pragma unroll
        for (int mt = 0; mt < 2; mt++) {
            int r_lo = row0 + mrow0 + mt * 16 + crow;
            int r_hi = r_lo + 8;
            float d_lo = (r_lo < n) ? g_dinv[r_lo] : 0.f;
            float d_hi = (r_hi < n) ? g_dinv[r_hi] : 0.f;
            #pragma unroll
            for (int nt = 0; nt < 8; nt++) {
                int col = ncol0 + nt * 8 + ccol;
                if (r_lo < n)
                    g_hs16[r_lo * 64 + (col >> 1)] =
                        __floats2half2_rn(acc[nt][mt][0] * d_lo, acc[nt][mt][1] * d_lo);
                if (r_hi < n)
                    g_hs16[r_hi * 64 + (col >> 1)] =
                        __floats2half2_rn(acc[nt][mt][2] * d_hi, acc[nt][mt][3] * d_hi);
            }
        }
    }
}

// ---------------- Aggregation core: warp per dst node; fp16 gather, fp32 accum ----------------
__device__ __forceinline__ float4 agg_row(int gw, int lane) {
    const uint2* hp = (const uint2*)g_hs16;

    float4 acc;
    {
        uint2 u = hp[gw * 32 + lane];
        float2 f0 = __half22float2(*(__half2*)&u.x);
        float2 f1 = __half22float2(*(__half2*)&u.y);
        acc.x = f0.x; acc.y = f0.y; acc.z = f1.x; acc.w = f1.y;
    }

    int s = g_rowptr[gw];
    int e = g_rowptr[gw + 1];
    for (int b = s; b < e; b += 32) {
        int idx = (b + lane < e) ? g_col[b + lane] : 0;
        int cnt = min(32, e - b);
        int j = 0;
        for (; j + 4 <= cnt; j += 4) {
            int s0 = __shfl_sync(0xffffffffu, idx, j);
            int s1 = __shfl_sync(0xffffffffu, idx, j + 1);
            int s2 = __shfl_sync(0xffffffffu, idx, j + 2);
            int s3 = __shfl_sync(0xffffffffu, idx, j + 3);
            uint2 u0 = hp[s0 * 32 + lane];
            uint2 u1 = hp[s1 * 32 + lane];
            uint2 u2 = hp[s2 * 32 + lane];
            uint2 u3 = hp[s3 * 32 + lane];
            float2 a0 = __half22float2(*(__half2*)&u0.x), b0 = __half22float2(*(__half2*)&u0.y);
            float2 a1 = __half22float2(*(__half2*)&u1.x), b1 = __half22float2(*(__half2*)&u1.y);
            float2 a2 = __half22float2(*(__half2*)&u2.x), b2 = __half22float2(*(__half2*)&u2.y);
            float2 a3 = __half22float2(*(__half2*)&u3.x), b3 = __half22float2(*(__half2*)&u3.y);
            acc.x += (a0.x + a1.x) + (a2.x + a3.x);
            acc.y += (a0.y + a1.y) + (a2.y + a3.y);
            acc.z += (b0.x + b1.x) + (b2.x + b3.x);
            acc.w += (b0.y + b1.y) + (b2.y + b3.y);
        }
        for (; j < cnt; j++) {
            int sj = __shfl_sync(0xffffffffu, idx, j);
            uint2 u = hp[sj * 32 + lane];
            float2 a = __half22float2(*(__half2*)&u.x);
            float2 bq = __half22float2(*(__half2*)&u.y);
            acc.x += a.x; acc.y += a.y; acc.z += bq.x; acc.w += bq.y;
        }
    }
    return acc;
}

// Layer-1 agg: out = dinv*acc + bias, stored bf16 (feeds GEMM2 A)
__global__ void k_agg_mid(const float* __restrict__ bias, int n) {
    int gw = (blockIdx.x * blockDim.x + threadIdx.x) >> 5;
    int lane = threadIdx.x & 31;
    if (gw >= n) return;

    float4 acc = agg_row(gw, lane);
    float di = g_dinv[gw];
    float4 bb = ((const float4*)bias)[lane];
    __nv_bfloat162 o01, o23;
    o01.x = __float2bfloat16_rn(di * acc.x + bb.x);
    o01.y = __float2bfloat16_rn(di * acc.y + bb.y);
    o23.x = __float2bfloat16_rn(di * acc.z + bb.z);
    o23.y = __float2bfloat16_rn(di * acc.w + bb.w);
    uint2 pk;
    pk.x = *(uint32_t*)&o01;
    pk.y = *(uint32_t*)&o23;
    ((uint2*)g_Ab)[gw * 32 + lane] = pk;
}

// Layer-2 agg: out = relu(dinv*acc + bias), stored fp16 (feeds final)
__global__ void k_agg_fin(const float* __restrict__ bias, int n) {
    int gw = (blockIdx.x * blockDim.x + threadIdx.x) >> 5;
    int lane = threadIdx.x & 31;
    if (gw >= n) return;

    float4 acc = agg_row(gw, lane);
    float di = g_dinv[gw];
    float4 bb = ((const float4*)bias)[lane];
    float o0 = fmaxf(di * acc.x + bb.x, 0.f);
    float o1 = fmaxf(di * acc.y + bb.y, 0.f);
    float o2 = fmaxf(di * acc.z + bb.z, 0.f);
    float o3 = fmaxf(di * acc.w + bb.w, 0.f);
    __half2 h01 = __floats2half2_rn(o0, o1);
    __half2 h23 = __floats2half2_rn(o2, o3);
    uint2 pk;
    pk.x = *(uint32_t*)&h01;
    pk.y = *(uint32_t*)&h23;
    ((uint2*)g_h2)[gw * 32 + lane] = pk;
}

// ---------------- Final: out = log_softmax(h2 @ Wout + bout), thread per row ----------------
__global__ void k_final(const float* __restrict__ Wout,
                        const float* __restrict__ bout,
                        float* __restrict__ out, int n) {
    __shared__ float Ws[NF * NC];
    __shared__ float bs[NC];
    int t = threadIdx.x;
    for (int i = t; i < NF * NC; i += blockDim.x) Ws[i] = Wout[i];
    if (t < NC) bs[t] = bout[t];
    __syncthreads();

    int row = blockIdx.x * blockDim.x + t;
    if (row >= n) return;

    float acc[NC];
    #pragma unroll
    for (int c = 0; c < NC; c++) acc[c] = bs[c];

    const uint2* H2  = (const uint2*)g_h2;
    const float4* Ws4 = (const float4*)Ws;
    for (int k4 = 0; k4 < NF / 4; k4++) {
        uint2 u = H2[row * 32 + k4];
        float2 fa = __half22float2(*(__half2*)&u.x);
        float2 fb = __half22float2(*(__half2*)&u.y);
        float xv0 = fa.x, xv1 = fa.y, xv2 = fb.x, xv3 = fb.y;
        #pragma unroll
        for (int c4 = 0; c4 < NC / 4; c4++) {
            float4 w0 = Ws4[(k4 * 4 + 0) * (NC / 4) + c4];
            float4 w1 = Ws4[(k4 * 4 + 1) * (NC / 4) + c4];
            float4 w2 = Ws4[(k4 * 4 + 2) * (NC / 4) + c4];
            float4 w3 = Ws4[(k4 * 4 + 3) * (NC / 4) + c4];
            acc[c4 * 4 + 0] += xv0 * w0.x + xv1 * w1.x + xv2 * w2.x + xv3 * w3.x;
            acc[c4 * 4 + 1] += xv0 * w0.y + xv1 * w1.y + xv2 * w2.y + xv3 * w3.y;
            acc[c4 * 4 + 2] += xv0 * w0.z + xv1 * w1.z + xv2 * w2.z + xv3 * w3.z;
            acc[c4 * 4 + 3] += xv0 * w0.w + xv1 * w1.w + xv2 * w2.w + xv3 * w3.w;
        }
    }

    float m = acc[0];
    #pragma unroll
    for (int c = 1; c < NC; c++) m = fmaxf(m, acc[c]);
    float ssum = 0.f;
    #pragma unroll
    for (int c = 0; c < NC; c++) ssum += __expf(acc[c] - m);
    float ls = m + __logf(ssum);
    #pragma unroll
    for (int c = 0; c < NC; c++) out[row * NC + c] = acc[c] - ls;
}

// ---------------- launch ----------------
extern "C" void kernel_launch(void* const* d_in, const int* in_sizes, int n_in,
                              void* d_out, int out_size) {
    const float* x    = (const float*)d_in[0];
    const void*  ei   = d_in[1];
    const float* Win  = (const float*)d_in[2];
    const float* bin  = (const float*)d_in[3];
    const float* W1   = (const float*)d_in[4];
    const float* b1   = (const float*)d_in[5];
    const float* Wout = (const float*)d_in[6];
    const float* bout = (const float*)d_in[7];
    float* out = (float*)d_out;

    int n = in_sizes[0] / NF;       // 50000
    int E = in_sizes[1] / 2;        // 800000
    int nb = (n + SCAN_TILE - 1) / SCAN_TILE;

    cudaFuncSetAttribute(k_gemm_mma, cudaFuncAttributeMaxDynamicSharedMemorySize,
                         SM_TOTAL);

    // CSR build (every call; no caching allowed)
    k_zero   <<<(n + 255) / 256, 256>>>(n);
    k_detect <<<1, 32>>>((const unsigned int*)ei);
    k_decode <<<(E + 255) / 256, 256>>>(ei, E);
    k_scan1  <<<nb, SCAN_TILE>>>(n);
    k_scan2  <<<1, 64>>>(nb, n);
    k_scan3  <<<nb, SCAN_TILE>>>(n);
    k_scatter<<<(E + 255) / 256, 256>>>(ei, E);

    int gemm_blocks = (n + 127) / 128;     // 391
    int agg_blocks  = (n * 32 + 255) / 256;

    // layer 1
    k_wsplit  <<<64, 256>>>(Win);
    k_gemm_mma<<<gemm_blocks, 256, SM_TOTAL>>>(x, 0, n);
    k_agg_mid <<<agg_blocks, 256>>>(bin, n);
    // layer 2
    k_wsplit  <<<64, 256>>>(W1);
    k_gemm_mma<<<gemm_blocks, 256, SM_TOTAL>>>(nullptr, 1, n);
    k_agg_fin <<<agg_blocks, 256>>>(b1, n);
    // output
    k_final<<<(n + 255) / 256, 256>>>(Wout, bout, out, n);
}

// round 7
// speedup vs baseline: 1.8943x; 1.3426x over previous
#include <cuda_runtime.h>
#include <cuda_bf16.h>
#include <cuda_fp16.h>
#include <cstdint>

#define N_NODES_MAX 50000
#define E_MAX       800000
#define NF          128
#define NC          40
#define SCAN_TILE   1024
#define NB_MAX      ((N_NODES_MAX + SCAN_TILE - 1) / SCAN_TILE)   // 49

// ---------------- scratch (static device globals; no allocation) ----------------
__device__ int   g_dst[E_MAX];
__device__ int   g_pos[E_MAX];
__device__ int   g_col[E_MAX];
__device__ int   g_deg[N_NODES_MAX];
__device__ int   g_rowptr[N_NODES_MAX + 1];
__device__ int   g_aggval[NB_MAX];
__device__ int   g_aggflag[NB_MAX];
__device__ float g_dinv[N_NODES_MAX];
__device__ __align__(16) __half2        g_hs16[N_NODES_MAX * 64]; // dinv*(X@W), fp16
__device__ __align__(16) __half2        g_h2[N_NODES_MAX * 64];   // layer2 agg out, fp16
__device__ __align__(16) __nv_bfloat16  g_Ab[N_NODES_MAX * NF];   // layer1 agg out, bf16
__device__ __align__(16) __nv_bfloat16  g_WT1[NF * NF];           // Win^T bf16
__device__ __align__(16) __nv_bfloat16  g_WT2[NF * NF];           // W1^T bf16
__device__ __align__(16) __half         g_WoT[NC * NF];           // Wout^T fp16
__device__ int   g_flag64;

// ---------------- weight prep (one launch): Win/W1 -> bf16 W^T, Wout -> fp16 W^T ----
__global__ void k_prep_w(const float* __restrict__ Win,
                         const float* __restrict__ W1,
                         const float* __restrict__ Wout) {
    int i = blockIdx.x * blockDim.x + threadIdx.x;    // 37888 = 148*256
    if (i < 16384) {
        int k = i >> 7, nn = i & 127;
        g_WT1[nn * NF + k] = __float2bfloat16_rn(Win[i]);
    } else if (i < 32768) {
        int j = i - 16384;
        int k = j >> 7, nn = j & 127;
        g_WT2[nn * NF + k] = __float2bfloat16_rn(W1[j]);
    } else if (i < 32768 + NF * NC) {
        int j = i - 32768;
        int k = j / NC, c = j % NC;
        g_WoT[c * NF + k] = __float2half(Wout[j]);
    }
}

// ---------------- zero + detect (one launch) ----------------
__global__ void k_zero_detect(const unsigned int* __restrict__ ei_words, int n) {
    int i = blockIdx.x * blockDim.x + threadIdx.x;
    if (i < n) g_deg[i] = 0;
    if (i < NB_MAX) g_aggflag[i] = 0;
    if (blockIdx.x == 0 && threadIdx.x < 32) {
        unsigned v = ei_words[2 * threadIdx.x + 1];
        unsigned mask = __ballot_sync(0xffffffffu, v != 0u);
        if (threadIdx.x == 0) g_flag64 = (mask == 0u) ? 1 : 0;
    }
}

__global__ void k_decode(const void* __restrict__ ei, int E) {
    int e = blockIdx.x * blockDim.x + threadIdx.x;
    if (e >= E) return;
    int d;
    if (g_flag64) d = (int)((const long long*)ei)[E + e];
    else          d = ((const int*)ei)[E + e];
    g_dst[e] = d;
    g_pos[e] = atomicAdd(&g_deg[d], 1);
}

// ---------------- single-kernel scan with decoupled lookback ----------------
__global__ void k_scan(int n, int nb) {
    __shared__ int warpsum[32];
    __shared__ int exoff_sh;
    int b = blockIdx.x;
    int i = b * SCAN_TILE + threadIdx.x;
    int lane = threadIdx.x & 31;
    int w    = threadIdx.x >> 5;
    int v = (i < n) ? g_deg[i] : 0;

    int incl = v;
    #pragma unroll
    for (int off = 1; off < 32; off <<= 1) {
        int tt = __shfl_up_sync(0xffffffffu, incl, off);
        if (lane >= off) incl += tt;
    }
    if (lane == 31) warpsum[w] = incl;
    __syncthreads();
    if (w == 0) {
        int s = warpsum[lane];
        #pragma unroll
        for (int off = 1; off < 32; off <<= 1) {
            int tt = __shfl_up_sync(0xffffffffu, s, off);
            if (lane >= off) s += tt;
        }
        warpsum[lane] = s;
    }
    __syncthreads();
    int total = warpsum[31];

    // publish this block's aggregate
    if (threadIdx.x == 0) {
        g_aggval[b] = total;
        __threadfence();
        atomicExch(&g_aggflag[b], 1);
    }

    // lookback: warp 0 gathers all predecessor aggregates in parallel
    if (w == 0) {
        if (lane == 0) exoff_sh = 0;
        int sumprev = 0;
        for (int base = 0; base < b; base += 32) {
            int j = base + lane;
            int pv = 0;
            if (j < b) {
                while (atomicAdd(&g_aggflag[j], 0) == 0) {}
                __threadfence();
                pv = g_aggval[j];
            }
            #pragma unroll
            for (int off = 16; off > 0; off >>= 1)
                pv += __shfl_down_sync(0xffffffffu, pv, off);
            if (lane == 0) sumprev += pv;
        }
        if (lane == 0) exoff_sh = sumprev;
    }
    __syncthreads();
    int exoff = exoff_sh;

    int excl = exoff + incl - v + (w > 0 ? warpsum[w - 1] : 0);
    if (i < n) {
        g_rowptr[i] = excl;
        g_dinv[i]   = rsqrtf(1.0f + (float)v);
    }
    if (b == nb - 1 && threadIdx.x == 0) g_rowptr[n] = exoff + total;
}

__global__ void k_scatter(const void* __restrict__ ei, int E) {
    int e = blockIdx.x * blockDim.x + threadIdx.x;
    if (e >= E) return;
    int s;
    if (g_flag64) s = (int)((const long long*)ei)[e];
    else          s = ((const int*)ei)[e];
    int d = g_dst[e];
    g_col[g_rowptr[d] + g_pos[e]] = s;
}

// ---------------- HMMA GEMM: hs16[row] = fp16( dinv[row] * (X[row] @ W) ) ----------------
#define SM_A     0
#define SM_B     32768
#define SM_TOTAL 65536

__device__ __forceinline__ uint32_t sm_u32(const void* p) {
    uint32_t r;
    asm("{ .reg .u64 t; cvta.to.shared.u64 t, %1; cvt.u32.u64 %0, t; }"
        : "=r"(r) : "l"(p));
    return r;
}

__global__ void __launch_bounds__(256, 2)
k_gemm_mma(const float* __restrict__ Xext, int use_internal, int n) {
    extern __shared__ char sm[];
    uint32_t smb = sm_u32(sm);

    int t = threadIdx.x;
    int lane = t & 31;
    int w = t >> 5;
    int row0 = blockIdx.x * 128;
    int mrow0 = (w & 3) * 32;
    int ncol0 = (w >> 2) * 64;

    if (use_internal) {
        const uint4* Ab4 = (const uint4*)g_Ab;
        for (int i = t; i < 128 * 16; i += 256) {
            int r  = i >> 4;
            int ch = i & 15;
            int gr = row0 + r;
            uint4 v = (gr < n) ? Ab4[gr * 16 + ch] : make_uint4(0, 0, 0, 0);
            uint32_t off = (uint32_t)(r * 256 + ((ch ^ (r & 7)) << 4));
            *(uint4*)(sm + SM_A + off) = v;
        }
    } else {
        const float4* X4 = (const float4*)Xext;
        for (int i = t; i < 128 * 32; i += 256) {
            int r  = i >> 5;
            int c4 = i & 31;
            int gr = row0 + r;
            float4 v = (gr < n) ? X4[gr * 32 + c4]
                                : make_float4(0.f, 0.f, 0.f, 0.f);
            int k0 = c4 * 4;
            uint32_t off = (uint32_t)(r * 256 +
                           (((k0 >> 3) ^ (r & 7)) << 4) + (k0 & 7) * 2);
            __nv_bfloat162 h01, h23;
            h01.x = __float2bfloat16_rn(v.x); h01.y = __float2bfloat16_rn(v.y);
            h23.x = __float2bfloat16_rn(v.z); h23.y = __float2bfloat16_rn(v.w);
            *(__nv_bfloat162*)(sm + SM_A + off)     = h01;
            *(__nv_bfloat162*)(sm + SM_A + off + 4) = h23;
        }
    }
    {
        const uint4* Wt4 = use_internal ? (const uint4*)g_WT2 : (const uint4*)g_WT1;
        for (int i = t; i < 128 * 16; i += 256) {
            int nn = i >> 4;
            int ch = i & 15;
            uint4 v = Wt4[nn * 16 + ch];
            uint32_t off = (uint32_t)(nn * 256 + ((ch ^ (nn & 7)) << 4));
            *(uint4*)(sm + SM_B + off) = v;
        }
    }
    __syncthreads();

    float acc[8][2][4];
    #pragma unroll
    for (int nt = 0; nt < 8; nt++)
        #pragma unroll
        for (int mt = 0; mt < 2; mt++)
            #pragma unroll
            for (int q = 0; q < 4; q++) acc[nt][mt][q] = 0.f;

    int a_row_off = ((lane >> 3) & 1) * 8 + (lane & 7);
    int a_chsel   = lane >> 4;
    int b_row     = lane & 7;
    int b_chsel   = (lane >> 3) & 1;

    #pragma unroll
    for (int ks = 0; ks < 8; ks++) {
        uint32_t a[2][4];
        #pragma unroll
        for (int mt = 0; mt < 2; mt++) {
            int row = mrow0 + mt * 16 + a_row_off;
            int ch  = ks * 2 + a_chsel;
            uint32_t addr = smb + SM_A + (uint32_t)(row * 256 + ((ch ^ (row & 7)) << 4));
            asm volatile(
                "ldmatrix.sync.aligned.m8n8.x4.shared.b16 {%0,%1,%2,%3}, [%4];"
                : "=r"(a[mt][0]), "=r"(a[mt][1]), "=r"(a[mt][2]), "=r"(a[mt][3])
                : "r"(addr));
        }
        #pragma unroll
        for (int nt = 0; nt < 8; nt++) {
            int row = ncol0 + nt * 8 + b_row;
            int ch  = ks * 2 + b_chsel;
            uint32_t addr = smb + SM_B + (uint32_t)(row * 256 + ((ch ^ (row & 7)) << 4));
            uint32_t bfr[2];
            asm volatile(
                "ldmatrix.sync.aligned.m8n8.x2.shared.b16 {%0,%1}, [%2];"
                : "=r"(bfr[0]), "=r"(bfr[1]) : "r"(addr));
            #pragma unroll
            for (int mt = 0; mt < 2; mt++) {
                asm volatile(
                    "mma.sync.aligned.m16n8k16.row.col.f32.bf16.bf16.f32 "
                    "{%0,%1,%2,%3}, {%4,%5,%6,%7}, {%8,%9}, {%0,%1,%2,%3};"
                    : "+f"(acc[nt][mt][0]), "+f"(acc[nt][mt][1]),
                      "+f"(acc[nt][mt][2]), "+f"(acc[nt][mt][3])
                    : "r"(a[mt][0]), "r"(a[mt][1]), "r"(a[mt][2]), "r"(a[mt][3]),
                      "r"(bfr[0]), "r"(bfr[1]));
            }
        }
    }

    {
        int crow = lane >> 2;
        int ccol = (lane & 3) * 2;
        #pragma unroll
        for (int mt = 0; mt < 2; mt++) {
            int r_lo = row0 + mrow0 + mt * 16 + crow;
            int r_hi = r_lo + 8;
            float d_lo = (r_lo < n) ? g_dinv[r_lo] : 0.f;
            float d_hi = (r_hi < n) ? g_dinv[r_hi] : 0.f;
            #pragma unroll
            for (int nt = 0; nt < 8; nt++) {
                int col = ncol0 + nt * 8 + ccol;
                if (r_lo < n)
                    g_hs16[r_lo * 64 + (col >> 1)] =
                        __floats2half2_rn(acc[nt][mt][0] * d_lo, acc[nt][mt][1] * d_lo);
                if (r_hi < n)
                    g_hs16[r_hi * 64 + (col >> 1)] =
                        __floats2half2_rn(acc[nt][mt][2] * d_hi, acc[nt][mt][3] * d_hi);
            }
        }
    }
}

// ---------------- Aggregation core: warp per dst node; fp16 gather, fp32 accum ----------------
__device__ __forceinline__ float4 agg_row(int gw, int lane) {
    const uint2* hp = (const uint2*)g_hs16;

    float4 acc;
    {
        uint2 u = hp[gw * 32 + lane];
        float2 f0 = __half22float2(*(__half2*)&u.x);
        float2 f1 = __half22float2(*(__half2*)&u.y);
        acc.x = f0.x; acc.y = f0.y; acc.z = f1.x; acc.w = f1.y;
    }

    int s = g_rowptr[gw];
    int e = g_rowptr[gw + 1];
    for (int b = s; b < e; b += 32) {
        int idx = (b + lane < e) ? g_col[b + lane] : 0;
        int cnt = min(32, e - b);
        int j = 0;
        for (; j + 4 <= cnt; j += 4) {
            int s0 = __shfl_sync(0xffffffffu, idx, j);
            int s1 = __shfl_sync(0xffffffffu, idx, j + 1);
            int s2 = __shfl_sync(0xffffffffu, idx, j + 2);
            int s3 = __shfl_sync(0xffffffffu, idx, j + 3);
            uint2 u0 = hp[s0 * 32 + lane];
            uint2 u1 = hp[s1 * 32 + lane];
            uint2 u2 = hp[s2 * 32 + lane];
            uint2 u3 = hp[s3 * 32 + lane];
            float2 a0 = __half22float2(*(__half2*)&u0.x), b0 = __half22float2(*(__half2*)&u0.y);
            float2 a1 = __half22float2(*(__half2*)&u1.x), b1 = __half22float2(*(__half2*)&u1.y);
            float2 a2 = __half22float2(*(__half2*)&u2.x), b2 = __half22float2(*(__half2*)&u2.y);
            float2 a3 = __half22float2(*(__half2*)&u3.x), b3 = __half22float2(*(__half2*)&u3.y);
            acc.x += (a0.x + a1.x) + (a2.x + a3.x);
            acc.y += (a0.y + a1.y) + (a2.y + a3.y);
            acc.z += (b0.x + b1.x) + (b2.x + b3.x);
            acc.w += (b0.y + b1.y) + (b2.y + b3.y);
        }
        for (; j < cnt; j++) {
            int sj = __shfl_sync(0xffffffffu, idx, j);
            uint2 u = hp[sj * 32 + lane];
            float2 a = __half22float2(*(__half2*)&u.x);
            float2 bq = __half22float2(*(__half2*)&u.y);
            acc.x += a.x; acc.y += a.y; acc.z += bq.x; acc.w += bq.y;
        }
    }
    return acc;
}

__global__ void k_agg_mid(const float* __restrict__ bias, int n) {
    int gw = (blockIdx.x * blockDim.x + threadIdx.x) >> 5;
    int lane = threadIdx.x & 31;
    if (gw >= n) return;

    float4 acc = agg_row(gw, lane);
    float di = g_dinv[gw];
    float4 bb = ((const float4*)bias)[lane];
    __nv_bfloat162 o01, o23;
    o01.x = __float2bfloat16_rn(di * acc.x + bb.x);
    o01.y = __float2bfloat16_rn(di * acc.y + bb.y);
    o23.x = __float2bfloat16_rn(di * acc.z + bb.z);
    o23.y = __float2bfloat16_rn(di * acc.w + bb.w);
    uint2 pk;
    pk.x = *(uint32_t*)&o01;
    pk.y = *(uint32_t*)&o23;
    ((uint2*)g_Ab)[gw * 32 + lane] = pk;
}

__global__ void k_agg_fin(const float* __restrict__ bias, int n) {
    int gw = (blockIdx.x * blockDim.x + threadIdx.x) >> 5;
    int lane = threadIdx.x & 31;
    if (gw >= n) return;

    float4 acc = agg_row(gw, lane);
    float di = g_dinv[gw];
    float4 bb = ((const float4*)bias)[lane];
    float o0 = fmaxf(di * acc.x + bb.x, 0.f);
    float o1 = fmaxf(di * acc.y + bb.y, 0.f);
    float o2 = fmaxf(di * acc.z + bb.z, 0.f);
    float o3 = fmaxf(di * acc.w + bb.w, 0.f);
    __half2 h01 = __floats2half2_rn(o0, o1);
    __half2 h23 = __floats2half2_rn(o2, o3);
    uint2 pk;
    pk.x = *(uint32_t*)&h01;
    pk.y = *(uint32_t*)&h23;
    ((uint2*)g_h2)[gw * 32 + lane] = pk;
}

// ---------------- Final via HMMA: out = log_softmax(h2 @ Wout + bout) ----------------
// CTA: 128 rows, 8 warps, warp = 16 rows x 40 cols (5 n-tiles of m16n8k16 f16).
#define SMF_A     0
#define SMF_B     32768                   // 40 rows x 256 B = 10240
#define SMF_BIAS  (SMF_B + 10240)         // 40 floats
#define SMF_TOTAL (SMF_BIAS + 256)

__global__ void __launch_bounds__(256, 2)
k_final_mma(const float* __restrict__ bout, float* __restrict__ out, int n) {
    extern __shared__ char sm[];
    uint32_t smb = sm_u32(sm);
    float* bsm = (float*)(sm + SMF_BIAS);

    int t = threadIdx.x;
    int lane = t & 31;
    int w = t >> 5;
    int row0 = blockIdx.x * 128;

    // stage A = h2 tile (fp16, 256 B/row, swizzled)
    {
        const uint4* H4 = (const uint4*)g_h2;
        for (int i = t; i < 128 * 16; i += 256) {
            int r  = i >> 4;
            int ch = i & 15;
            int gr = row0 + r;
            uint4 v = (gr < n) ? H4[gr * 16 + ch] : make_uint4(0, 0, 0, 0);
            uint32_t off = (uint32_t)(r * 256 + ((ch ^ (r & 7)) << 4));
            *(uint4*)(sm + SMF_A + off) = v;
        }
    }
    // stage B = WoT (fp16, 40 rows x 256 B, swizzled) + bias
    {
        const uint4* Wo4 = (const uint4*)g_WoT;
        for (int i = t; i < NC * 16; i += 256) {
            int nn = i >> 4;
            int ch = i & 15;
            uint4 v = Wo4[nn * 16 + ch];
            uint32_t off = (uint32_t)(nn * 256 + ((ch ^ (nn & 7)) << 4));
            *(uint4*)(sm + SMF_B + off) = v;
        }
        if (t < NC) bsm[t] = bout[t];
    }
    __syncthreads();

    int mrow0 = w * 16;
    float acc[5][4];
    #pragma unroll
    for (int nt = 0; nt < 5; nt++)
        #pragma unroll
        for (int q = 0; q < 4; q++) acc[nt][q] = 0.f;

    int a_row_off = ((lane >> 3) & 1) * 8 + (lane & 7);
    int a_chsel   = lane >> 4;
    int b_row     = lane & 7;
    int b_chsel   = (lane >> 3) & 1;

    #pragma unroll
    for (int ks = 0; ks < 8; ks++) {
        uint32_t a[4];
        {
            int row = mrow0 + a_row_off;
            int ch  = ks * 2 + a_chsel;
            uint32_t addr = smb + SMF_A + (uint32_t)(row * 256 + ((ch ^ (row & 7)) << 4));
            asm volatile(
                "ldmatrix.sync.aligned.m8n8.x4.shared.b16 {%0,%1,%2,%3}, [%4];"
                : "=r"(a[0]), "=r"(a[1]), "=r"(a[2]), "=r"(a[3]) : "r"(addr));
        }
        #pragma unroll
        for (int nt = 0; nt < 5; nt++) {
            int row = nt * 8 + b_row;
            int ch  = ks * 2 + b_chsel;
            uint32_t addr = smb + SMF_B + (uint32_t)(row * 256 + ((ch ^ (row & 7)) << 4));
            uint32_t bfr[2];
            asm volatile(
                "ldmatrix.sync.aligned.m8n8.x2.shared.b16 {%0,%1}, [%2];"
                : "=r"(bfr[0]), "=r"(bfr[1]) : "r"(addr));
            asm volatile(
                "mma.sync.aligned.m16n8k16.row.col.f32.f16.f16.f32 "
                "{%0,%1,%2,%3}, {%4,%5,%6,%7}, {%8,%9}, {%0,%1,%2,%3};"
                : "+f"(acc[nt][0]), "+f"(acc[nt][1]), "+f"(acc[nt][2]), "+f"(acc[nt][3])
                : "r"(a[0]), "r"(a[1]), "r"(a[2]), "r"(a[3]),
                  "r"(bfr[0]), "r"(bfr[1]));
        }
    }

    // epilogue: bias, per-row log-softmax via 4-lane xor reduce, write
    {
        int g = lane >> 2;
        int q = lane & 3;
        int r0 = row0 + mrow0 + g;
        int r1 = r0 + 8;

        float v0[5][2], v1[5][2];
        #pragma unroll
        for (int nt = 0; nt < 5; nt++) {
            int col = nt * 8 + q * 2;
            v0[nt][0] = acc[nt][0] + bsm[col];
            v0[nt][1] = acc[nt][1] + bsm[col + 1];
            v1[nt][0] = acc[nt][2] + bsm[col];
            v1[nt][1] = acc[nt][3] + bsm[col + 1];
        }
        float m0 = v0[0][0], m1 = v1[0][0];
        #pragma unroll
        for (int nt = 0; nt < 5; nt++) {
            m0 = fmaxf(m0, fmaxf(v0[nt][0], v0[nt][1]));
            m1 = fmaxf(m1, fmaxf(v1[nt][0], v1[nt][1]));
        }
        #pragma unroll
        for (int o = 1; o <= 2; o <<= 1) {
            m0 = fmaxf(m0, __shfl_xor_sync(0xffffffffu, m0, o));
            m1 = fmaxf(m1, __shfl_xor_sync(0xffffffffu, m1, o));
        }
        float s0 = 0.f, s1 = 0.f;
        #pragma unroll
        for (int nt = 0; nt < 5; nt++) {
            s0 += __expf(v0[nt][0] - m0) + __expf(v0[nt][1] - m0);
            s1 += __expf(v1[nt][0] - m1) + __expf(v1[nt][1] - m1);
        }
        #pragma unroll
        for (int o = 1; o <= 2; o <<= 1) {
            s0 += __shfl_xor_sync(0xffffffffu, s0, o);
            s1 += __shfl_xor_sync(0xffffffffu, s1, o);
        }
        float ls0 = m0 + __logf(s0);
        float ls1 = m1 + __logf(s1);

        #pragma unroll
        for (int nt = 0; nt < 5; nt++) {
            int col = nt * 8 + q * 2;
            if (r0 < n) {
                float2 o2; o2.x = v0[nt][0] - ls0; o2.y = v0[nt][1] - ls0;
                *(float2*)&out[r0 * NC + col] = o2;
            }
            if (r1 < n) {
                float2 o2; o2.x = v1[nt][0] - ls1; o2.y = v1[nt][1] - ls1;
                *(float2*)&out[r1 * NC + col] = o2;
            }
        }
    }
}

// ---------------- launch ----------------
extern "C" void kernel_launch(void* const* d_in, const int* in_sizes, int n_in,
                              void* d_out, int out_size) {
    const float* x    = (const float*)d_in[0];
    const void*  ei   = d_in[1];
    const float* Win  = (const float*)d_in[2];
    const float* bin  = (const float*)d_in[3];
    const float* W1   = (const float*)d_in[4];
    const float* b1   = (const float*)d_in[5];
    const float* Wout = (const float*)d_in[6];
    const float* bout = (const float*)d_in[7];
    float* out = (float*)d_out;

    int n = in_sizes[0] / NF;       // 50000
    int E = in_sizes[1] / 2;        // 800000
    int nb = (n + SCAN_TILE - 1) / SCAN_TILE;

    cudaFuncSetAttribute(k_gemm_mma, cudaFuncAttributeMaxDynamicSharedMemorySize,
                         SM_TOTAL);
    cudaFuncSetAttribute(k_final_mma, cudaFuncAttributeMaxDynamicSharedMemorySize,
                         SMF_TOTAL);

    int gemm_blocks = (n + 127) / 128;     // 391
    int agg_blocks  = (n * 32 + 255) / 256;

    k_prep_w     <<<148, 256>>>(Win, W1, Wout);
    k_zero_detect<<<(n + 255) / 256, 256>>>((const unsigned int*)ei, n);
    k_decode     <<<(E + 255) / 256, 256>>>(ei, E);
    k_scan       <<<nb, SCAN_TILE>>>(n, nb);
    k_scatter    <<<(E + 255) / 256, 256>>>(ei, E);

    // layer 1
    k_gemm_mma<<<gemm_blocks, 256, SM_TOTAL>>>(x, 0, n);
    k_agg_mid <<<agg_blocks, 256>>>(bin, n);
    // layer 2
    k_gemm_mma<<<gemm_blocks, 256, SM_TOTAL>>>(nullptr, 1, n);
    k_agg_fin <<<agg_blocks, 256>>>(b1, n);
    // output
    k_final_mma<<<gemm_blocks, 256, SMF_TOTAL>>>(bout, out, n);
}